// round 7
// baseline (speedup 1.0000x reference)
#include <cuda_runtime.h>
#include <cuda_bf16.h>
#include <cstdint>

#define N_NODES 40000
#define DIMF    128
#define N_EDGES 640000

// ---- scratch (no allocs allowed) ----
__device__ int   g_deg[N_NODES];          // in-degree (int)
__device__ int   g_off[N_NODES];          // CSR offsets
__device__ int   g_cur[N_NODES];          // scatter cursors
__device__ float g_cnt[N_NODES];          // in-degree (float, for GEMM)
__device__ int   g_esrc[N_EDGES];         // src indices sorted by dst
__device__ float g_agg[N_NODES * DIMF];   // neighbor-sum buffer
__device__ float g_h[N_NODES * DIMF];     // layer-1 output

// ---------------------------------------------------------------------------
// CSR build (once per call; graph shared by both layers)
// ---------------------------------------------------------------------------
__global__ void init_deg_kernel() {
    int i = blockIdx.x * blockDim.x + threadIdx.x;
    if (i < N_NODES) g_deg[i] = 0;
}

__global__ void hist_kernel(const int* __restrict__ ei) {
    int e = blockIdx.x * blockDim.x + threadIdx.x;
    if (e >= N_EDGES) return;
    int d = ei[N_EDGES + e];
    if ((unsigned)d < N_NODES) atomicAdd(&g_deg[d], 1);
}

// single-block exclusive prefix scan over 40k degrees; also emits cur + float cnt
__global__ __launch_bounds__(1024) void prefix_kernel() {
    __shared__ int ssum[1024];
    const int t  = threadIdx.x;
    const int CH = (N_NODES + 1023) / 1024;      // 40
    const int base = t * CH;

    int s = 0;
    for (int i = 0; i < CH; ++i) {
        int idx = base + i;
        if (idx < N_NODES) s += g_deg[idx];
    }
    ssum[t] = s;
    __syncthreads();
    for (int d = 1; d < 1024; d <<= 1) {
        int v = (t >= d) ? ssum[t - d] : 0;
        __syncthreads();
        ssum[t] += v;
        __syncthreads();
    }
    int run = (t == 0) ? 0 : ssum[t - 1];
    for (int i = 0; i < CH; ++i) {
        int idx = base + i;
        if (idx >= N_NODES) break;
        int dg = g_deg[idx];
        g_off[idx] = run;
        g_cur[idx] = run;
        g_cnt[idx] = (float)dg;
        run += dg;
    }
}

__global__ void sort_kernel(const int* __restrict__ ei) {
    int e = blockIdx.x * blockDim.x + threadIdx.x;
    if (e >= N_EDGES) return;
    int s = ei[e];
    int d = ei[N_EDGES + e];
    if ((unsigned)s >= N_NODES || (unsigned)d >= N_NODES) return;
    int pos = atomicAdd(&g_cur[d], 1);
    g_esrc[pos] = s;
}

// ---------------------------------------------------------------------------
// aggregate: one warp per dst node. Indices fetched 32-at-a-time with ONE
// coalesced LDG per warp (lane-parallel, shfl-broadcast). Gathers issued in
// groups of 8 into 8 independent accumulators (MLP=8). One 512B store/node.
// ---------------------------------------------------------------------------
__global__ __launch_bounds__(256) void agg_kernel(const float* __restrict__ feat) {
    const int w    = blockIdx.x * (blockDim.x >> 5) + (threadIdx.x >> 5);
    const int lane = threadIdx.x & 31;
    if (w >= N_NODES) return;

    const int deg   = g_deg[w];
    const int start = g_off[w];

    float4 a0 = make_float4(0.f, 0.f, 0.f, 0.f), a1 = a0, a2 = a0, a3 = a0,
           a4 = a0, a5 = a0, a6 = a0, a7 = a0;

    for (int base = 0; base < deg; base += 32) {
        const int n = min(32, deg - base);
        // one coalesced index load per warp
        int idx = (lane < n) ? __ldg(&g_esrc[start + base + lane]) : 0;

        int j = 0;
        const int full = n & ~7;
#pragma unroll 1
        for (; j < full; j += 8) {
            int s0 = __shfl_sync(0xffffffffu, idx, j + 0);
            int s1 = __shfl_sync(0xffffffffu, idx, j + 1);
            int s2 = __shfl_sync(0xffffffffu, idx, j + 2);
            int s3 = __shfl_sync(0xffffffffu, idx, j + 3);
            int s4 = __shfl_sync(0xffffffffu, idx, j + 4);
            int s5 = __shfl_sync(0xffffffffu, idx, j + 5);
            int s6 = __shfl_sync(0xffffffffu, idx, j + 6);
            int s7 = __shfl_sync(0xffffffffu, idx, j + 7);
            float4 v0 = reinterpret_cast<const float4*>(feat + (size_t)s0 * DIMF)[lane];
            float4 v1 = reinterpret_cast<const float4*>(feat + (size_t)s1 * DIMF)[lane];
            float4 v2 = reinterpret_cast<const float4*>(feat + (size_t)s2 * DIMF)[lane];
            float4 v3 = reinterpret_cast<const float4*>(feat + (size_t)s3 * DIMF)[lane];
            float4 v4 = reinterpret_cast<const float4*>(feat + (size_t)s4 * DIMF)[lane];
            float4 v5 = reinterpret_cast<const float4*>(feat + (size_t)s5 * DIMF)[lane];
            float4 v6 = reinterpret_cast<const float4*>(feat + (size_t)s6 * DIMF)[lane];
            float4 v7 = reinterpret_cast<const float4*>(feat + (size_t)s7 * DIMF)[lane];
            a0.x += v0.x; a0.y += v0.y; a0.z += v0.z; a0.w += v0.w;
            a1.x += v1.x; a1.y += v1.y; a1.z += v1.z; a1.w += v1.w;
            a2.x += v2.x; a2.y += v2.y; a2.z += v2.z; a2.w += v2.w;
            a3.x += v3.x; a3.y += v3.y; a3.z += v3.z; a3.w += v3.w;
            a4.x += v4.x; a4.y += v4.y; a4.z += v4.z; a4.w += v4.w;
            a5.x += v5.x; a5.y += v5.y; a5.z += v5.z; a5.w += v5.w;
            a6.x += v6.x; a6.y += v6.y; a6.z += v6.z; a6.w += v6.w;
            a7.x += v7.x; a7.y += v7.y; a7.z += v7.z; a7.w += v7.w;
        }
#pragma unroll 1
        for (; j < n; ++j) {
            int s = __shfl_sync(0xffffffffu, idx, j);
            float4 v = reinterpret_cast<const float4*>(feat + (size_t)s * DIMF)[lane];
            a0.x += v.x; a0.y += v.y; a0.z += v.z; a0.w += v.w;
        }
    }

    float4 acc;
    acc.x = (a0.x + a1.x) + (a2.x + a3.x) + ((a4.x + a5.x) + (a6.x + a7.x));
    acc.y = (a0.y + a1.y) + (a2.y + a3.y) + ((a4.y + a5.y) + (a6.y + a7.y));
    acc.z = (a0.z + a1.z) + (a2.z + a3.z) + ((a4.z + a5.z) + (a6.z + a7.z));
    acc.w = (a0.w + a1.w) + (a2.w + a3.w) + ((a4.w + a5.w) + (a6.w + a7.w));
    reinterpret_cast<float4*>(g_agg + (size_t)w * DIMF)[lane] = acc;
}

// ---------------------------------------------------------------------------
// Tensor-core (tf32 mma.sync) fused SAGE GEMM with on-the-fly mean norm:
//   out[m][n] = relu( (1/max(cnt[m],1)) * sum_k A0[m][k]*W0[n][k]
//                    + sum_k A1[m][k]*W1[n][k] + bias[n] )
// ---------------------------------------------------------------------------
#define BM 128
#define BK 16
#define LDP 132   // padded smem row stride (uint32 elems)

__device__ __forceinline__ uint32_t f2tf32(float v) {
    uint32_t t;
    asm("cvt.rna.tf32.f32 %0, %1;" : "=r"(t) : "f"(v));
    return t;
}

__global__ __launch_bounds__(256, 2) void gemm_tc_kernel(
        const float* A0, const float* __restrict__ A1,
        const float* __restrict__ cnt,
        const float* __restrict__ W0, const float* __restrict__ W1,
        const float* __restrict__ bias, float* __restrict__ out) {
    __shared__ uint32_t As[BK * LDP];
    __shared__ uint32_t Bs[BK * LDP];

    const int tid   = threadIdx.x;
    const int m0    = blockIdx.x * BM;
    const int lane  = tid & 31;
    const int warp  = tid >> 5;
    const int warpM = warp & 1;
    const int warpN = warp >> 1;
    const int lr    = lane >> 2;
    const int lc    = lane & 3;

    const int r0 = tid >> 2;
    const int r1 = r0 + 64;
    const int q  = tid & 3;

    const int gm0 = m0 + r0, gm1 = m0 + r1;
    const float s0 = (gm0 < N_NODES) ? __frcp_rn(fmaxf(__ldg(&cnt[gm0]), 1.f)) : 0.f;
    const float s1 = (gm1 < N_NODES) ? __frcp_rn(fmaxf(__ldg(&cnt[gm1]), 1.f)) : 0.f;

    float acc[4][4][4];
#pragma unroll
    for (int i = 0; i < 4; ++i)
#pragma unroll
        for (int j = 0; j < 4; ++j)
#pragma unroll
            for (int f = 0; f < 4; ++f) acc[i][j][f] = 0.f;

    const float4 f4z = make_float4(0.f, 0.f, 0.f, 0.f);
    float4 a0r, a1r, b0r, b1r;

    auto load_tile = [&](int kt, float4& av0, float4& av1, float4& bv0, float4& bv1) {
        const float* A = (kt < 8) ? A0 : A1;
        const float* W = (kt < 8) ? W0 : W1;
        const float sc0 = (kt < 8) ? s0 : 1.f;
        const float sc1 = (kt < 8) ? s1 : 1.f;
        const int k0 = (kt & 7) * BK + q * 4;
        av0 = (gm0 < N_NODES) ? *reinterpret_cast<const float4*>(A + (size_t)gm0 * DIMF + k0) : f4z;
        av1 = (gm1 < N_NODES) ? *reinterpret_cast<const float4*>(A + (size_t)gm1 * DIMF + k0) : f4z;
        av0.x *= sc0; av0.y *= sc0; av0.z *= sc0; av0.w *= sc0;
        av1.x *= sc1; av1.y *= sc1; av1.z *= sc1; av1.w *= sc1;
        bv0 = *reinterpret_cast<const float4*>(W + (size_t)r0 * DIMF + k0);
        bv1 = *reinterpret_cast<const float4*>(W + (size_t)r1 * DIMF + k0);
    };

    load_tile(0, a0r, a1r, b0r, b1r);

#pragma unroll 1
    for (int kt = 0; kt < 16; ++kt) {
        __syncthreads();
        const int kb = q * 4;
        As[(kb + 0) * LDP + r0] = f2tf32(a0r.x);  As[(kb + 1) * LDP + r0] = f2tf32(a0r.y);
        As[(kb + 2) * LDP + r0] = f2tf32(a0r.z);  As[(kb + 3) * LDP + r0] = f2tf32(a0r.w);
        As[(kb + 0) * LDP + r1] = f2tf32(a1r.x);  As[(kb + 1) * LDP + r1] = f2tf32(a1r.y);
        As[(kb + 2) * LDP + r1] = f2tf32(a1r.z);  As[(kb + 3) * LDP + r1] = f2tf32(a1r.w);
        Bs[(kb + 0) * LDP + r0] = f2tf32(b0r.x);  Bs[(kb + 1) * LDP + r0] = f2tf32(b0r.y);
        Bs[(kb + 2) * LDP + r0] = f2tf32(b0r.z);  Bs[(kb + 3) * LDP + r0] = f2tf32(b0r.w);
        Bs[(kb + 0) * LDP + r1] = f2tf32(b1r.x);  Bs[(kb + 1) * LDP + r1] = f2tf32(b1r.y);
        Bs[(kb + 2) * LDP + r1] = f2tf32(b1r.z);  Bs[(kb + 3) * LDP + r1] = f2tf32(b1r.w);
        __syncthreads();

        if (kt < 15) load_tile(kt + 1, a0r, a1r, b0r, b1r);

#pragma unroll
        for (int s = 0; s < BK; s += 8) {
            uint32_t bf0[4], bf1[4];
#pragma unroll
            for (int nt = 0; nt < 4; ++nt) {
                const int n = warpN * 32 + nt * 8 + lr;
                bf0[nt] = Bs[(s + lc) * LDP + n];
                bf1[nt] = Bs[(s + lc + 4) * LDP + n];
            }
#pragma unroll
            for (int mt = 0; mt < 4; ++mt) {
                const int m = warpM * 64 + mt * 16 + lr;
                uint32_t a0 = As[(s + lc) * LDP + m];
                uint32_t a1 = As[(s + lc) * LDP + m + 8];
                uint32_t a2 = As[(s + lc + 4) * LDP + m];
                uint32_t a3 = As[(s + lc + 4) * LDP + m + 8];
#pragma unroll
                for (int nt = 0; nt < 4; ++nt) {
                    asm volatile(
                        "mma.sync.aligned.m16n8k8.row.col.f32.tf32.tf32.f32 "
                        "{%0,%1,%2,%3}, {%4,%5,%6,%7}, {%8,%9}, {%0,%1,%2,%3};"
                        : "+f"(acc[mt][nt][0]), "+f"(acc[mt][nt][1]),
                          "+f"(acc[mt][nt][2]), "+f"(acc[mt][nt][3])
                        : "r"(a0), "r"(a1), "r"(a2), "r"(a3),
                          "r"(bf0[nt]), "r"(bf1[nt]));
                }
            }
        }
    }

    // epilogue: + bias, relu
#pragma unroll
    for (int nt = 0; nt < 4; ++nt) {
        const int n = warpN * 32 + nt * 8 + 2 * lc;
        const float bv0 = __ldg(&bias[n]);
        const float bv1 = __ldg(&bias[n + 1]);
#pragma unroll
        for (int mt = 0; mt < 4; ++mt) {
            const int r = m0 + warpM * 64 + mt * 16 + lr;
            if (r < N_NODES) {
                float2 v;
                v.x = fmaxf(acc[mt][nt][0] + bv0, 0.f);
                v.y = fmaxf(acc[mt][nt][1] + bv1, 0.f);
                *reinterpret_cast<float2*>(out + (size_t)r * DIMF + n) = v;
            }
            if (r + 8 < N_NODES) {
                float2 v;
                v.x = fmaxf(acc[mt][nt][2] + bv0, 0.f);
                v.y = fmaxf(acc[mt][nt][3] + bv1, 0.f);
                *reinterpret_cast<float2*>(out + (size_t)(r + 8) * DIMF + n) = v;
            }
        }
    }
}

// ---------------------------------------------------------------------------
// launch
// ---------------------------------------------------------------------------
extern "C" void kernel_launch(void* const* d_in, const int* in_sizes, int n_in,
                              void* d_out, int out_size) {
    const float* x   = (const float*)d_in[0];
    const int*   ei  = (const int*)d_in[1];
    const float* W1l = (const float*)d_in[2];
    const float* b1l = (const float*)d_in[3];
    const float* W1r = (const float*)d_in[4];
    const float* W2l = (const float*)d_in[5];
    const float* b2l = (const float*)d_in[6];
    const float* W2r = (const float*)d_in[7];
    float* out = (float*)d_out;

    const int node_grid = (N_NODES + 255) / 256;
    const int edge_grid = (N_EDGES + 255) / 256;
    const int agg_grid  = (N_NODES + 7) / 8;             // warp per node
    const int gemm_grid = (N_NODES + BM - 1) / BM;       // 313

    static float* p_agg = nullptr;
    static float* p_h   = nullptr;
    static float* p_cnt = nullptr;
    if (!p_agg) {
        cudaGetSymbolAddress((void**)&p_agg, g_agg);
        cudaGetSymbolAddress((void**)&p_h,   g_h);
        cudaGetSymbolAddress((void**)&p_cnt, g_cnt);
    }

    // ---- CSR build (shared by both layers) ----
    init_deg_kernel<<<node_grid, 256>>>();
    hist_kernel<<<edge_grid, 256>>>(ei);
    prefix_kernel<<<1, 1024>>>();
    sort_kernel<<<edge_grid, 256>>>(ei);

    // ---- layer 1 ----
    agg_kernel<<<agg_grid, 256>>>(x);
    gemm_tc_kernel<<<gemm_grid, 256>>>(p_agg, x, p_cnt, W1l, W1r, b1l, p_h);

    // ---- layer 2 ----
    agg_kernel<<<agg_grid, 256>>>(p_h);
    gemm_tc_kernel<<<gemm_grid, 256>>>(p_agg, p_h, p_cnt, W2l, W2r, b2l, out);
}

// round 8
// speedup vs baseline: 1.0496x; 1.0496x over previous
#include <cuda_runtime.h>
#include <cuda_bf16.h>
#include <cstdint>

#define N_NODES 40000
#define DIMF    128
#define N_EDGES 640000
#define EPW     16            // edges per warp

// ---- scratch (no allocs allowed) ----
__device__ int   g_degs[N_NODES];         // src out-degree (for sort)
__device__ int   g_cur[N_NODES];          // sort cursors
__device__ int   g_ssrc[N_EDGES];         // src, sorted by src
__device__ int   g_sdst[N_EDGES];         // dst, sorted by src
__device__ float g_cnt[N_NODES];          // dst in-degree (float, for mean)
__device__ float g_agg[N_NODES * DIMF];   // neighbor-sum buffer
__device__ float g_h[N_NODES * DIMF];     // layer-1 output

// ---------------------------------------------------------------------------
// zero agg + cnt + src-degree
// ---------------------------------------------------------------------------
__global__ void zero_kernel() {
    int i = blockIdx.x * blockDim.x + threadIdx.x;
    const int tot4 = N_NODES * DIMF / 4;
    if (i < tot4) reinterpret_cast<float4*>(g_agg)[i] = make_float4(0.f, 0.f, 0.f, 0.f);
    if (i < N_NODES) { g_cnt[i] = 0.f; g_degs[i] = 0; }
}

// ---------------------------------------------------------------------------
// CSR-by-src build (once per call; reused by both layers)
// ---------------------------------------------------------------------------
__global__ void hist_kernel(const int* __restrict__ ei) {
    int e = blockIdx.x * blockDim.x + threadIdx.x;
    if (e >= N_EDGES) return;
    int s = ei[e];
    if ((unsigned)s < N_NODES) atomicAdd(&g_degs[s], 1);
}

// single-block exclusive prefix scan over 40k src-degrees -> cursors
__global__ __launch_bounds__(1024) void prefix_kernel() {
    __shared__ int ssum[1024];
    const int t  = threadIdx.x;
    const int CH = (N_NODES + 1023) / 1024;      // 40
    const int base = t * CH;

    int s = 0;
    for (int i = 0; i < CH; ++i) {
        int idx = base + i;
        if (idx < N_NODES) s += g_degs[idx];
    }
    ssum[t] = s;
    __syncthreads();
    for (int d = 1; d < 1024; d <<= 1) {
        int v = (t >= d) ? ssum[t - d] : 0;
        __syncthreads();
        ssum[t] += v;
        __syncthreads();
    }
    int run = (t == 0) ? 0 : ssum[t - 1];
    for (int i = 0; i < CH; ++i) {
        int idx = base + i;
        if (idx >= N_NODES) break;
        g_cur[idx] = run;
        run += g_degs[idx];
    }
}

__global__ void sort_kernel(const int* __restrict__ ei) {
    int e = blockIdx.x * blockDim.x + threadIdx.x;
    if (e >= N_EDGES) return;
    int s = ei[e];
    int d = ei[N_EDGES + e];
    if ((unsigned)s >= N_NODES || (unsigned)d >= N_NODES) return;
    int pos = atomicAdd(&g_cur[s], 1);
    g_ssrc[pos] = s;
    g_sdst[pos] = d;
}

// ---------------------------------------------------------------------------
// scatter over src-sorted edges: EPW edges per warp (round-5 structure).
// Within a batch nearly all edges share src -> gather rows are L1 hits after
// the first touch, cutting L2 read traffic ~16x. RED writes unchanged.
// ---------------------------------------------------------------------------
__global__ __launch_bounds__(256) void scatter_kernel(
        const float* __restrict__ feat,
        const int* __restrict__ esrc,
        const int* __restrict__ edst,
        int do_count) {
    const int wid  = blockIdx.x * (blockDim.x >> 5) + (threadIdx.x >> 5);
    const int lane = threadIdx.x & 31;
    const int base = wid * EPW;
    if (base >= N_EDGES) return;

    const int nrem = min(EPW, N_EDGES - base);
    const int off  = lane & 15;
    int idx = -1;
    if (off < nrem)
        idx = (lane < 16) ? esrc[base + off] : edst[base + off];

    // dst in-degree: one atomic per dst lane (layer 1 only)
    if (do_count && lane >= 16 && (unsigned)idx < N_NODES)
        atomicAdd(&g_cnt[idx], 1.0f);

#pragma unroll
    for (int j = 0; j < EPW; ++j) {
        int s = __shfl_sync(0xffffffffu, idx, j);
        int d = __shfl_sync(0xffffffffu, idx, 16 + j);
        if ((unsigned)s >= N_NODES || (unsigned)d >= N_NODES) continue;
        float4 v = reinterpret_cast<const float4*>(feat + (size_t)s * DIMF)[lane];
        float* p = g_agg + (size_t)d * DIMF + lane * 4;
        asm volatile("red.global.add.v4.f32 [%0], {%1, %2, %3, %4};"
                     :: "l"(p), "f"(v.x), "f"(v.y), "f"(v.z), "f"(v.w)
                     : "memory");
    }
}

// ---------------------------------------------------------------------------
// Tensor-core (tf32 mma.sync) fused SAGE GEMM with on-the-fly mean norm:
//   out[m][n] = relu( (1/max(cnt[m],1)) * sum_k A0[m][k]*W0[n][k]
//                    + sum_k A1[m][k]*W1[n][k] + bias[n] )
// If zero_buf != null, epilogue zero-fills zero_buf rows [m0, m0+BM).
// ---------------------------------------------------------------------------
#define BM 128
#define BK 16
#define LDP 132   // padded smem row stride (uint32 elems)

__device__ __forceinline__ uint32_t f2tf32(float v) {
    uint32_t t;
    asm("cvt.rna.tf32.f32 %0, %1;" : "=r"(t) : "f"(v));
    return t;
}

__global__ __launch_bounds__(256, 2) void gemm_tc_kernel(
        const float* A0, const float* __restrict__ A1,
        const float* __restrict__ cnt,
        const float* __restrict__ W0, const float* __restrict__ W1,
        const float* __restrict__ bias, float* __restrict__ out,
        float* zero_buf) {
    __shared__ uint32_t As[BK * LDP];
    __shared__ uint32_t Bs[BK * LDP];

    const int tid   = threadIdx.x;
    const int m0    = blockIdx.x * BM;
    const int lane  = tid & 31;
    const int warp  = tid >> 5;
    const int warpM = warp & 1;
    const int warpN = warp >> 1;
    const int lr    = lane >> 2;
    const int lc    = lane & 3;

    const int r0 = tid >> 2;
    const int r1 = r0 + 64;
    const int q  = tid & 3;

    const int gm0 = m0 + r0, gm1 = m0 + r1;
    const float s0 = (gm0 < N_NODES) ? __frcp_rn(fmaxf(__ldg(&cnt[gm0]), 1.f)) : 0.f;
    const float s1 = (gm1 < N_NODES) ? __frcp_rn(fmaxf(__ldg(&cnt[gm1]), 1.f)) : 0.f;

    float acc[4][4][4];
#pragma unroll
    for (int i = 0; i < 4; ++i)
#pragma unroll
        for (int j = 0; j < 4; ++j)
#pragma unroll
            for (int f = 0; f < 4; ++f) acc[i][j][f] = 0.f;

    const float4 f4z = make_float4(0.f, 0.f, 0.f, 0.f);
    float4 a0r, a1r, b0r, b1r;

    auto load_tile = [&](int kt, float4& av0, float4& av1, float4& bv0, float4& bv1) {
        const float* A = (kt < 8) ? A0 : A1;
        const float* W = (kt < 8) ? W0 : W1;
        const float sc0 = (kt < 8) ? s0 : 1.f;
        const float sc1 = (kt < 8) ? s1 : 1.f;
        const int k0 = (kt & 7) * BK + q * 4;
        av0 = (gm0 < N_NODES) ? *reinterpret_cast<const float4*>(A + (size_t)gm0 * DIMF + k0) : f4z;
        av1 = (gm1 < N_NODES) ? *reinterpret_cast<const float4*>(A + (size_t)gm1 * DIMF + k0) : f4z;
        av0.x *= sc0; av0.y *= sc0; av0.z *= sc0; av0.w *= sc0;
        av1.x *= sc1; av1.y *= sc1; av1.z *= sc1; av1.w *= sc1;
        bv0 = *reinterpret_cast<const float4*>(W + (size_t)r0 * DIMF + k0);
        bv1 = *reinterpret_cast<const float4*>(W + (size_t)r1 * DIMF + k0);
    };

    load_tile(0, a0r, a1r, b0r, b1r);

#pragma unroll 1
    for (int kt = 0; kt < 16; ++kt) {
        __syncthreads();
        const int kb = q * 4;
        As[(kb + 0) * LDP + r0] = f2tf32(a0r.x);  As[(kb + 1) * LDP + r0] = f2tf32(a0r.y);
        As[(kb + 2) * LDP + r0] = f2tf32(a0r.z);  As[(kb + 3) * LDP + r0] = f2tf32(a0r.w);
        As[(kb + 0) * LDP + r1] = f2tf32(a1r.x);  As[(kb + 1) * LDP + r1] = f2tf32(a1r.y);
        As[(kb + 2) * LDP + r1] = f2tf32(a1r.z);  As[(kb + 3) * LDP + r1] = f2tf32(a1r.w);
        Bs[(kb + 0) * LDP + r0] = f2tf32(b0r.x);  Bs[(kb + 1) * LDP + r0] = f2tf32(b0r.y);
        Bs[(kb + 2) * LDP + r0] = f2tf32(b0r.z);  Bs[(kb + 3) * LDP + r0] = f2tf32(b0r.w);
        Bs[(kb + 0) * LDP + r1] = f2tf32(b1r.x);  Bs[(kb + 1) * LDP + r1] = f2tf32(b1r.y);
        Bs[(kb + 2) * LDP + r1] = f2tf32(b1r.z);  Bs[(kb + 3) * LDP + r1] = f2tf32(b1r.w);
        __syncthreads();

        if (kt < 15) load_tile(kt + 1, a0r, a1r, b0r, b1r);

#pragma unroll
        for (int s = 0; s < BK; s += 8) {
            uint32_t bf0[4], bf1[4];
#pragma unroll
            for (int nt = 0; nt < 4; ++nt) {
                const int n = warpN * 32 + nt * 8 + lr;
                bf0[nt] = Bs[(s + lc) * LDP + n];
                bf1[nt] = Bs[(s + lc + 4) * LDP + n];
            }
#pragma unroll
            for (int mt = 0; mt < 4; ++mt) {
                const int m = warpM * 64 + mt * 16 + lr;
                uint32_t a0 = As[(s + lc) * LDP + m];
                uint32_t a1 = As[(s + lc) * LDP + m + 8];
                uint32_t a2 = As[(s + lc + 4) * LDP + m];
                uint32_t a3 = As[(s + lc + 4) * LDP + m + 8];
#pragma unroll
                for (int nt = 0; nt < 4; ++nt) {
                    asm volatile(
                        "mma.sync.aligned.m16n8k8.row.col.f32.tf32.tf32.f32 "
                        "{%0,%1,%2,%3}, {%4,%5,%6,%7}, {%8,%9}, {%0,%1,%2,%3};"
                        : "+f"(acc[mt][nt][0]), "+f"(acc[mt][nt][1]),
                          "+f"(acc[mt][nt][2]), "+f"(acc[mt][nt][3])
                        : "r"(a0), "r"(a1), "r"(a2), "r"(a3),
                          "r"(bf0[nt]), "r"(bf1[nt]));
                }
            }
        }
    }

    // epilogue: + bias, relu
#pragma unroll
    for (int nt = 0; nt < 4; ++nt) {
        const int n = warpN * 32 + nt * 8 + 2 * lc;
        const float bv0 = __ldg(&bias[n]);
        const float bv1 = __ldg(&bias[n + 1]);
#pragma unroll
        for (int mt = 0; mt < 4; ++mt) {
            const int r = m0 + warpM * 64 + mt * 16 + lr;
            if (r < N_NODES) {
                float2 v;
                v.x = fmaxf(acc[mt][nt][0] + bv0, 0.f);
                v.y = fmaxf(acc[mt][nt][1] + bv1, 0.f);
                *reinterpret_cast<float2*>(out + (size_t)r * DIMF + n) = v;
            }
            if (r + 8 < N_NODES) {
                float2 v;
                v.x = fmaxf(acc[mt][nt][2] + bv0, 0.f);
                v.y = fmaxf(acc[mt][nt][3] + bv1, 0.f);
                *reinterpret_cast<float2*>(out + (size_t)(r + 8) * DIMF + n) = v;
            }
        }
    }

    // fused zeroing of this block's agg rows for the next layer
    if (zero_buf) {
        const float4 z = make_float4(0.f, 0.f, 0.f, 0.f);
#pragma unroll
        for (int i = 0; i < 16; ++i) {
            int e   = tid + i * 256;
            int row = m0 + (e >> 5);
            if (row < N_NODES)
                reinterpret_cast<float4*>(zero_buf + (size_t)row * DIMF)[e & 31] = z;
        }
    }
}

// ---------------------------------------------------------------------------
// launch
// ---------------------------------------------------------------------------
extern "C" void kernel_launch(void* const* d_in, const int* in_sizes, int n_in,
                              void* d_out, int out_size) {
    const float* x   = (const float*)d_in[0];
    const int*   ei  = (const int*)d_in[1];
    const float* W1l = (const float*)d_in[2];
    const float* b1l = (const float*)d_in[3];
    const float* W1r = (const float*)d_in[4];
    const float* W2l = (const float*)d_in[5];
    const float* b2l = (const float*)d_in[6];
    const float* W2r = (const float*)d_in[7];
    float* out = (float*)d_out;

    const int tot4      = N_NODES * DIMF / 4;
    const int zero_grid = (tot4 + 255) / 256;
    const int edge_grid = (N_EDGES + 255) / 256;
    const int n_warps   = (N_EDGES + EPW - 1) / EPW;      // 40000 warps
    const int scat_grid = (n_warps + 7) / 8;              // 5000 blocks
    const int gemm_grid = (N_NODES + BM - 1) / BM;        // 313

    static float* p_agg  = nullptr;
    static float* p_h    = nullptr;
    static float* p_cnt  = nullptr;
    static int*   p_ssrc = nullptr;
    static int*   p_sdst = nullptr;
    if (!p_agg) {
        cudaGetSymbolAddress((void**)&p_agg,  g_agg);
        cudaGetSymbolAddress((void**)&p_h,    g_h);
        cudaGetSymbolAddress((void**)&p_cnt,  g_cnt);
        cudaGetSymbolAddress((void**)&p_ssrc, g_ssrc);
        cudaGetSymbolAddress((void**)&p_sdst, g_sdst);
    }

    // ---- CSR-by-src build (shared by both layers) ----
    zero_kernel<<<zero_grid, 256>>>();
    hist_kernel<<<edge_grid, 256>>>(ei);
    prefix_kernel<<<1, 1024>>>();
    sort_kernel<<<edge_grid, 256>>>(ei);

    // ---- layer 1 ----
    scatter_kernel<<<scat_grid, 256>>>(x, p_ssrc, p_sdst, 1);
    gemm_tc_kernel<<<gemm_grid, 256>>>(p_agg, x, p_cnt, W1l, W1r, b1l, p_h, p_agg);

    // ---- layer 2 ----
    scatter_kernel<<<scat_grid, 256>>>(p_h, p_ssrc, p_sdst, 0);
    gemm_tc_kernel<<<gemm_grid, 256>>>(p_agg, p_h, p_cnt, W2l, W2r, b2l, out, nullptr);
}

// round 9
// speedup vs baseline: 1.2507x; 1.1917x over previous
#include <cuda_runtime.h>
#include <cuda_bf16.h>
#include <cstdint>

#define N_NODES 40000
#define DIMF    128
#define N_EDGES 640000
#define EPW     16            // edges per warp

// ---- scratch (no allocs allowed) ----
__device__ float g_agg[N_NODES * DIMF];   // neighbor-sum buffer (unnormalized)
__device__ float g_cnt[N_NODES];          // in-degree (float)
__device__ float g_h[N_NODES * DIMF];     // layer-1 output

// ---------------------------------------------------------------------------
// zero agg + cnt (layer 1 only; layer-2 zeroing fused into GEMM1 epilogue)
// ---------------------------------------------------------------------------
__global__ void zero_kernel() {
    int i = blockIdx.x * blockDim.x + threadIdx.x;
    const int tot4 = N_NODES * DIMF / 4;
    if (i < tot4) reinterpret_cast<float4*>(g_agg)[i] = make_float4(0.f, 0.f, 0.f, 0.f);
    if (i < N_NODES) g_cnt[i] = 0.f;
}

// ---------------------------------------------------------------------------
// scatter: EPW edges per warp (round-5 proven config, 60.6us @ L2 wall).
// ---------------------------------------------------------------------------
__global__ __launch_bounds__(256) void scatter_kernel(
        const float* __restrict__ feat,
        const int* __restrict__ ei,
        int do_count) {
    const int wid  = blockIdx.x * (blockDim.x >> 5) + (threadIdx.x >> 5);
    const int lane = threadIdx.x & 31;
    const int base = wid * EPW;
    if (base >= N_EDGES) return;

    const int nrem = min(EPW, N_EDGES - base);
    int idx = -1;
    const int off = lane & 15;
    if (off < nrem)
        idx = ei[(lane < 16 ? base : N_EDGES + base) + off];

    if (do_count && lane >= 16 && (unsigned)idx < N_NODES)
        atomicAdd(&g_cnt[idx], 1.0f);

#pragma unroll
    for (int j = 0; j < EPW; ++j) {
        int s = __shfl_sync(0xffffffffu, idx, j);
        int d = __shfl_sync(0xffffffffu, idx, 16 + j);
        if ((unsigned)s >= N_NODES || (unsigned)d >= N_NODES) continue;
        float4 v = reinterpret_cast<const float4*>(feat + (size_t)s * DIMF)[lane];
        float* p = g_agg + (size_t)d * DIMF + lane * 4;
        asm volatile("red.global.add.v4.f32 [%0], {%1, %2, %3, %4};"
                     :: "l"(p), "f"(v.x), "f"(v.y), "f"(v.z), "f"(v.w)
                     : "memory");
    }
}

// ---------------------------------------------------------------------------
// Tensor-core (tf32 mma.sync) fused SAGE GEMM, DOUBLE-BUFFERED smem tiles:
//   out[m][n] = relu( (1/max(cnt[m],1)) * sum_k A0[m][k]*W0[n][k]
//                    + sum_k A1[m][k]*W1[n][k] + bias[n] )
// One __syncthreads per k-tile; STS(k+1) overlaps MMA(k); LDG prefetch ahead.
// ---------------------------------------------------------------------------
#define BM 128
#define BK 16
#define LDP 132   // padded smem row stride (uint32 elems)

__device__ __forceinline__ uint32_t f2tf32(float v) {
    uint32_t t;
    asm("cvt.rna.tf32.f32 %0, %1;" : "=r"(t) : "f"(v));
    return t;
}

__global__ __launch_bounds__(256, 2) void gemm_tc_kernel(
        const float* A0, const float* __restrict__ A1,
        const float* __restrict__ cnt,
        const float* __restrict__ W0, const float* __restrict__ W1,
        const float* __restrict__ bias, float* __restrict__ out,
        float* zero_buf) {
    __shared__ uint32_t As[2][BK * LDP];
    __shared__ uint32_t Bs[2][BK * LDP];

    const int tid   = threadIdx.x;
    const int m0    = blockIdx.x * BM;
    const int lane  = tid & 31;
    const int warp  = tid >> 5;
    const int warpM = warp & 1;        // 0..1 -> 64 rows each
    const int warpN = warp >> 1;       // 0..3 -> 32 cols each
    const int lr    = lane >> 2;       // 0..7
    const int lc    = lane & 3;        // 0..3

    const int r0 = tid >> 2;           // 0..63
    const int r1 = r0 + 64;            // 64..127
    const int q  = tid & 3;            // 0..3

    const int gm0 = m0 + r0, gm1 = m0 + r1;
    const float s0 = (gm0 < N_NODES) ? __frcp_rn(fmaxf(__ldg(&cnt[gm0]), 1.f)) : 0.f;
    const float s1 = (gm1 < N_NODES) ? __frcp_rn(fmaxf(__ldg(&cnt[gm1]), 1.f)) : 0.f;

    float acc[4][4][4];   // [m-tile][n-tile][frag]
#pragma unroll
    for (int i = 0; i < 4; ++i)
#pragma unroll
        for (int j = 0; j < 4; ++j)
#pragma unroll
            for (int f = 0; f < 4; ++f) acc[i][j][f] = 0.f;

    const float4 f4z = make_float4(0.f, 0.f, 0.f, 0.f);
    float4 a0r, a1r, b0r, b1r;

    auto load_tile = [&](int kt, float4& av0, float4& av1, float4& bv0, float4& bv1) {
        const float* A = (kt < 8) ? A0 : A1;
        const float* W = (kt < 8) ? W0 : W1;
        const float sc0 = (kt < 8) ? s0 : 1.f;
        const float sc1 = (kt < 8) ? s1 : 1.f;
        const int k0 = (kt & 7) * BK + q * 4;
        av0 = (gm0 < N_NODES) ? *reinterpret_cast<const float4*>(A + (size_t)gm0 * DIMF + k0) : f4z;
        av1 = (gm1 < N_NODES) ? *reinterpret_cast<const float4*>(A + (size_t)gm1 * DIMF + k0) : f4z;
        av0.x *= sc0; av0.y *= sc0; av0.z *= sc0; av0.w *= sc0;
        av1.x *= sc1; av1.y *= sc1; av1.z *= sc1; av1.w *= sc1;
        bv0 = *reinterpret_cast<const float4*>(W + (size_t)r0 * DIMF + k0);
        bv1 = *reinterpret_cast<const float4*>(W + (size_t)r1 * DIMF + k0);
    };

    auto store_tile = [&](int buf) {
        const int kb = q * 4;
        As[buf][(kb + 0) * LDP + r0] = f2tf32(a0r.x);  As[buf][(kb + 1) * LDP + r0] = f2tf32(a0r.y);
        As[buf][(kb + 2) * LDP + r0] = f2tf32(a0r.z);  As[buf][(kb + 3) * LDP + r0] = f2tf32(a0r.w);
        As[buf][(kb + 0) * LDP + r1] = f2tf32(a1r.x);  As[buf][(kb + 1) * LDP + r1] = f2tf32(a1r.y);
        As[buf][(kb + 2) * LDP + r1] = f2tf32(a1r.z);  As[buf][(kb + 3) * LDP + r1] = f2tf32(a1r.w);
        Bs[buf][(kb + 0) * LDP + r0] = f2tf32(b0r.x);  Bs[buf][(kb + 1) * LDP + r0] = f2tf32(b0r.y);
        Bs[buf][(kb + 2) * LDP + r0] = f2tf32(b0r.z);  Bs[buf][(kb + 3) * LDP + r0] = f2tf32(b0r.w);
        Bs[buf][(kb + 0) * LDP + r1] = f2tf32(b1r.x);  Bs[buf][(kb + 1) * LDP + r1] = f2tf32(b1r.y);
        Bs[buf][(kb + 2) * LDP + r1] = f2tf32(b1r.z);  Bs[buf][(kb + 3) * LDP + r1] = f2tf32(b1r.w);
    };

    // prologue: tile 0 into buffer 0
    load_tile(0, a0r, a1r, b0r, b1r);
    store_tile(0);
    __syncthreads();

#pragma unroll 1
    for (int kt = 0; kt < 16; ++kt) {
        const int buf = kt & 1;
        // prefetch next tile into registers (LDG latency hides under MMA)
        if (kt < 15) load_tile(kt + 1, a0r, a1r, b0r, b1r);

#pragma unroll
        for (int s = 0; s < BK; s += 8) {
            uint32_t bf0[4], bf1[4];
#pragma unroll
            for (int nt = 0; nt < 4; ++nt) {
                const int n = warpN * 32 + nt * 8 + lr;
                bf0[nt] = Bs[buf][(s + lc) * LDP + n];
                bf1[nt] = Bs[buf][(s + lc + 4) * LDP + n];
            }
#pragma unroll
            for (int mt = 0; mt < 4; ++mt) {
                const int m = warpM * 64 + mt * 16 + lr;
                uint32_t a0 = As[buf][(s + lc) * LDP + m];
                uint32_t a1 = As[buf][(s + lc) * LDP + m + 8];
                uint32_t a2 = As[buf][(s + lc + 4) * LDP + m];
                uint32_t a3 = As[buf][(s + lc + 4) * LDP + m + 8];
#pragma unroll
                for (int nt = 0; nt < 4; ++nt) {
                    asm volatile(
                        "mma.sync.aligned.m16n8k8.row.col.f32.tf32.tf32.f32 "
                        "{%0,%1,%2,%3}, {%4,%5,%6,%7}, {%8,%9}, {%0,%1,%2,%3};"
                        : "+f"(acc[mt][nt][0]), "+f"(acc[mt][nt][1]),
                          "+f"(acc[mt][nt][2]), "+f"(acc[mt][nt][3])
                        : "r"(a0), "r"(a1), "r"(a2), "r"(a3),
                          "r"(bf0[nt]), "r"(bf1[nt]));
                }
            }
        }

        if (kt < 15) {
            store_tile(buf ^ 1);   // write next tile; prev MMA on buf^1 done pre-sync
            __syncthreads();
        }
    }

    // epilogue: + bias, relu
#pragma unroll
    for (int nt = 0; nt < 4; ++nt) {
        const int n = warpN * 32 + nt * 8 + 2 * lc;
        const float bv0 = __ldg(&bias[n]);
        const float bv1 = __ldg(&bias[n + 1]);
#pragma unroll
        for (int mt = 0; mt < 4; ++mt) {
            const int r = m0 + warpM * 64 + mt * 16 + lr;
            if (r < N_NODES) {
                float2 v;
                v.x = fmaxf(acc[mt][nt][0] + bv0, 0.f);
                v.y = fmaxf(acc[mt][nt][1] + bv1, 0.f);
                *reinterpret_cast<float2*>(out + (size_t)r * DIMF + n) = v;
            }
            if (r + 8 < N_NODES) {
                float2 v;
                v.x = fmaxf(acc[mt][nt][2] + bv0, 0.f);
                v.y = fmaxf(acc[mt][nt][3] + bv1, 0.f);
                *reinterpret_cast<float2*>(out + (size_t)(r + 8) * DIMF + n) = v;
            }
        }
    }

    // fused zeroing of this block's agg rows for the next layer
    if (zero_buf) {
        const float4 z = make_float4(0.f, 0.f, 0.f, 0.f);
#pragma unroll
        for (int i = 0; i < 16; ++i) {
            int e   = tid + i * 256;
            int row = m0 + (e >> 5);
            if (row < N_NODES)
                reinterpret_cast<float4*>(zero_buf + (size_t)row * DIMF)[e & 31] = z;
        }
    }
}

// ---------------------------------------------------------------------------
// launch
// ---------------------------------------------------------------------------
extern "C" void kernel_launch(void* const* d_in, const int* in_sizes, int n_in,
                              void* d_out, int out_size) {
    const float* x   = (const float*)d_in[0];
    const int*   ei  = (const int*)d_in[1];
    const float* W1l = (const float*)d_in[2];
    const float* b1l = (const float*)d_in[3];
    const float* W1r = (const float*)d_in[4];
    const float* W2l = (const float*)d_in[5];
    const float* b2l = (const float*)d_in[6];
    const float* W2r = (const float*)d_in[7];
    float* out = (float*)d_out;

    const int tot4      = N_NODES * DIMF / 4;
    const int zero_grid = (tot4 + 255) / 256;
    const int n_warps   = (N_EDGES + EPW - 1) / EPW;      // 40000 warps
    const int scat_grid = (n_warps + 7) / 8;              // 5000 blocks
    const int gemm_grid = (N_NODES + BM - 1) / BM;        // 313

    static float* p_agg = nullptr;
    static float* p_h   = nullptr;
    static float* p_cnt = nullptr;
    if (!p_agg) {
        cudaGetSymbolAddress((void**)&p_agg, g_agg);
        cudaGetSymbolAddress((void**)&p_h,   g_h);
        cudaGetSymbolAddress((void**)&p_cnt, g_cnt);
    }

    // ---- layer 1 ----
    zero_kernel<<<zero_grid, 256>>>();
    scatter_kernel<<<scat_grid, 256>>>(x, ei, 1);
    gemm_tc_kernel<<<gemm_grid, 256>>>(p_agg, x, p_cnt, W1l, W1r, b1l, p_h, p_agg);

    // ---- layer 2 ----
    scatter_kernel<<<scat_grid, 256>>>(p_h, ei, 0);
    gemm_tc_kernel<<<gemm_grid, 256>>>(p_agg, p_h, p_cnt, W2l, W2r, b2l, out, nullptr);
}